// round 3
// baseline (speedup 1.0000x reference)
#include <cuda_runtime.h>
#include <cstdint>

// ---------------------------------------------------------------------------
// DCNv2 (offset conv -> modulated bilinear sampling -> 3x3 conv) + GroupNorm16
// B=4, Cin=Cout=256, H=W=64, K=3, stride=1, pad=1, groups=16, eps=1e-5
// All fp32. Main conv uses packed fma.rn.f32x2 (FFMA2) for 2x fp32 rate.
// ---------------------------------------------------------------------------

// Scratch (device globals -- no allocation allowed)
__device__ float g_Wt[9 * 256 * 256];          // W transposed: [k][c][o]
__device__ int   g_midx[4 * 9 * 4096 * 4];     // bilinear corner indices (clamped)
__device__ float g_mw[4 * 9 * 4096 * 4];       // corner weights * mask (0 if invalid)
__device__ float g_conv[4 * 256 * 4096];       // conv output (pre-GN, incl. bias)
__device__ float g_mu[64];                     // GN mean per (b,g)
__device__ float g_rs[64];                     // GN rsqrt(var+eps) per (b,g)

__device__ __forceinline__ unsigned long long dup2(float v) {
    unsigned int u = __float_as_uint(v);
    return ((unsigned long long)u << 32) | (unsigned long long)u;
}
__device__ __forceinline__ float lo32(unsigned long long v) {
    return __uint_as_float((unsigned int)v);
}
__device__ __forceinline__ float hi32(unsigned long long v) {
    return __uint_as_float((unsigned int)(v >> 32));
}
#define FMA2(d, a, b) asm("fma.rn.f32x2 %0, %1, %2, %0;" : "+l"(d) : "l"(a), "l"(b))

// ---------------------------------------------------------------------------
// Kernel 0: transpose weight [O][C][K] -> g_Wt [k][c][o]
// ---------------------------------------------------------------------------
__global__ void k_transpose(const float* __restrict__ w) {
    int o = blockIdx.x;  // 256 blocks
    for (int i = threadIdx.x; i < 2304; i += blockDim.x) {
        int c = i / 9, k = i - c * 9;
        g_Wt[(k * 256 + c) * 256 + o] = w[o * 2304 + i];
    }
}

// ---------------------------------------------------------------------------
// Kernel 1: offset conv (27 channels) fused with bilinear-meta generation.
// Grid: 256 = (b, h). 576 threads = (k in 0..8) x (p=w in 0..63).
// Thread (k,p) accumulates off_y (oc=k), off_x (oc=k+9), mask (oc=k+18),
// then emits 4 corner (index, weight*mask) pairs.
// ---------------------------------------------------------------------------
__global__ __launch_bounds__(576) void k_offset(const float* __restrict__ x,
                                                const float* __restrict__ wof,
                                                const float* __restrict__ bof) {
    __shared__ float xs[8][3][68];     // 8 c x 3 rows x (64+2 cols, padded)
    __shared__ float wsm[8][27][9];    // c, oc, tap

    int b = blockIdx.x >> 6, h = blockIdx.x & 63;
    int tid = threadIdx.x;
    int k = tid / 64, p = tid & 63;
    float a0 = 0.f, a1 = 0.f, a2 = 0.f;

    for (int c0 = 0; c0 < 256; c0 += 8) {
        // stage x rows h-1..h+1 (zero padded)
        for (int i = tid; i < 8 * 3 * 66; i += 576) {
            int c = i / 198, r = i - c * 198;
            int row = r / 66, col = r - row * 66 - 1;
            int y = h - 1 + row;
            float v = 0.f;
            if (y >= 0 && y < 64 && col >= 0 && col < 64)
                v = x[(((b * 256 + c0 + c) * 64) + y) * 64 + col];
            xs[c][row][col + 1] = v;
        }
        // stage offset-conv weights for this c chunk
        for (int i = tid; i < 1944; i += 576) {
            int oc = i / 72, r = i - oc * 72;
            int c = r / 9, j = r - c * 9;
            wsm[c][oc][j] = wof[oc * 2304 + c0 * 9 + r];
        }
        __syncthreads();
#pragma unroll
        for (int c = 0; c < 8; c++) {
            float w0[9], w1[9], w2[9];
#pragma unroll
            for (int j = 0; j < 9; j++) {
                w0[j] = wsm[c][k][j];
                w1[j] = wsm[c][k + 9][j];
                w2[j] = wsm[c][k + 18][j];
            }
#pragma unroll
            for (int j = 0; j < 9; j++) {
                float xv = xs[c][j / 3][p + (j - (j / 3) * 3)];
                a0 = fmaf(xv, w0[j], a0);
                a1 = fmaf(xv, w1[j], a1);
                a2 = fmaf(xv, w2[j], a2);
            }
        }
        __syncthreads();
    }
    a0 += bof[k]; a1 += bof[k + 9]; a2 += bof[k + 18];
    float m = 1.f / (1.f + __expf(-a2));           // sigmoid mask
    float py = (float)(h - 1 + k / 3) + a0;        // base_y + kgy + off_y
    float px = (float)(p - 1 + (k - (k / 3) * 3)) + a1;
    float y0f = floorf(py), x0f = floorf(px);
    float wy1 = py - y0f, wx1 = px - x0f;
    int y0 = (int)y0f, x0 = (int)x0f;
    size_t base = ((size_t)(b * 9 + k) * 4096 + (size_t)(h * 64 + p)) * 4;
#pragma unroll
    for (int j = 0; j < 4; j++) {
        int dy = j >> 1, dx = j & 1;
        int yy = y0 + dy, xx = x0 + dx;
        float wv = (dy ? wy1 : 1.f - wy1) * (dx ? wx1 : 1.f - wx1);
        bool valid = (yy >= 0) && (yy < 64) && (xx >= 0) && (xx < 64);
        int yc = min(max(yy, 0), 63), xc = min(max(xx, 0), 63);
        g_midx[base + j] = yc * 64 + xc;
        g_mw[base + j] = valid ? wv * m : 0.f;
    }
}

// ---------------------------------------------------------------------------
// Kernel 2: fused sampling + implicit GEMM (main deformable conv), FFMA2.
// Grid: 128 = (b in 0..3) x (32 tiles of 128 pixels). 512 threads.
// Thread = (to 0..31) x (tp 0..15): 8 outputs x 8 pixels, pixel pairs packed
// in f32x2. W duplicated as (w,w) pairs in smem; s kept scalar, loaded as
// natural (even,odd)-p pairs. Thread pixel set {4tp..4tp+3, 64+4tp..64+4tp+3}
// keeps every smem read lane-contiguous (conflict-free).
// ---------------------------------------------------------------------------
__global__ __launch_bounds__(512, 1) void k_main(const float* __restrict__ x,
                                                 const float* __restrict__ bias) {
    __shared__ unsigned long long sW2[16][256];  // 32 KB: dup (w,w) per c,o
    __shared__ float sS[16][128];                // 8 KB: sampled values
    __shared__ int   sIdx[128][4];               // 2 KB: corner indices
    __shared__ float sWgt[128][4];               // 2 KB: corner weights

    int b = blockIdx.x >> 5;
    int p0 = (blockIdx.x & 31) << 7;
    int tid = threadIdx.x;
    int to = tid >> 4, tp = tid & 15;
    int ob = to << 3;

    unsigned long long acc[8][4];
#pragma unroll
    for (int i = 0; i < 8; i++)
#pragma unroll
        for (int j = 0; j < 4; j++) acc[i][j] = 0ull;

    const float* xb0 = x + ((size_t)b << 20);
    int wc = tid >> 6;          // 0..7
    int wo = (tid & 63) << 2;   // 0..252

    float xr[16];               // prefetch staging for next c-chunk

    for (int k = 0; k < 9; k++) {
        {   // load bilinear meta for this (b,k,tile): exactly 1 pair per thread
            int mp = tid >> 2, mj = tid & 3;
            size_t mb = (((size_t)(b * 9 + k) << 12) + (size_t)(p0 + mp)) * 4 + mj;
            sIdx[mp][mj] = g_midx[mb];
            sWgt[mp][mj] = g_mw[mb];
        }
        __syncthreads();
        // prefetch x gathers for chunk 0
#pragma unroll
        for (int i = 0; i < 4; i++) {
            int v = tid + (i << 9);
            int c = v >> 7, pp = v & 127;
            const float* xb = xb0 + ((size_t)c << 12);
#pragma unroll
            for (int j = 0; j < 4; j++) xr[i * 4 + j] = xb[sIdx[pp][j]];
        }
        for (int ci = 0; ci < 16; ci++) {
            int c0 = ci << 4;
            // stage sampled values from prefetched registers
#pragma unroll
            for (int i = 0; i < 4; i++) {
                int v = tid + (i << 9);
                int c = v >> 7, pp = v & 127;
                float sv = sWgt[pp][0] * xr[i * 4 + 0] + sWgt[pp][1] * xr[i * 4 + 1]
                         + sWgt[pp][2] * xr[i * 4 + 2] + sWgt[pp][3] * xr[i * 4 + 3];
                sS[c][pp] = sv;
            }
            {   // stage W tile (dup pairs). 2 float4 per thread from L2.
                const float4 w4a = *(const float4*)&g_Wt[(((k << 8) + c0 + wc) << 8) + wo];
                const float4 w4b = *(const float4*)&g_Wt[(((k << 8) + c0 + wc + 8) << 8) + wo];
                ulonglong2 t;
                t.x = dup2(w4a.x); t.y = dup2(w4a.y); *((ulonglong2*)&sW2[wc][wo]) = t;
                t.x = dup2(w4a.z); t.y = dup2(w4a.w); *((ulonglong2*)&sW2[wc][wo + 2]) = t;
                t.x = dup2(w4b.x); t.y = dup2(w4b.y); *((ulonglong2*)&sW2[wc + 8][wo]) = t;
                t.x = dup2(w4b.z); t.y = dup2(w4b.w); *((ulonglong2*)&sW2[wc + 8][wo + 2]) = t;
            }
            __syncthreads();
            // prefetch next chunk's x gathers under the GEMM phase
            if (ci < 15) {
                int c0n = c0 + 16;
#pragma unroll
                for (int i = 0; i < 4; i++) {
                    int v = tid + (i << 9);
                    int c = v >> 7, pp = v & 127;
                    const float* xb = xb0 + ((size_t)(c0n + c) << 12);
#pragma unroll
                    for (int j = 0; j < 4; j++) xr[i * 4 + j] = xb[sIdx[pp][j]];
                }
            }
            // GEMM micro-loop: 16 c x (8 o-pairs x 4 p-pairs) FFMA2
#pragma unroll
            for (int cc = 0; cc < 16; cc++) {
                ulonglong2 wq0 = *(const ulonglong2*)&sW2[cc][ob];
                ulonglong2 wq1 = *(const ulonglong2*)&sW2[cc][ob + 2];
                ulonglong2 wq2 = *(const ulonglong2*)&sW2[cc][ob + 4];
                ulonglong2 wq3 = *(const ulonglong2*)&sW2[cc][ob + 6];
                const float* sp = &sS[cc][tp << 2];
                ulonglong2 sq0 = *(const ulonglong2*)sp;
                ulonglong2 sq1 = *(const ulonglong2*)(sp + 64);
                unsigned long long wv[8] = {wq0.x, wq0.y, wq1.x, wq1.y,
                                            wq2.x, wq2.y, wq3.x, wq3.y};
                unsigned long long sv[4] = {sq0.x, sq0.y, sq1.x, sq1.y};
#pragma unroll
                for (int i = 0; i < 8; i++)
#pragma unroll
                    for (int j = 0; j < 4; j++) FMA2(acc[i][j], wv[i], sv[j]);
            }
            __syncthreads();
        }
    }
    // epilogue: add bias, store fully-coalesced float4s
#pragma unroll
    for (int i = 0; i < 8; i++) {
        int o = ob + i;
        float bv = bias[o];
        float* op = g_conv + (((size_t)(b * 256 + o)) << 12) + p0;
        float4 r0, r1;
        r0.x = lo32(acc[i][0]) + bv; r0.y = hi32(acc[i][0]) + bv;
        r0.z = lo32(acc[i][1]) + bv; r0.w = hi32(acc[i][1]) + bv;
        r1.x = lo32(acc[i][2]) + bv; r1.y = hi32(acc[i][2]) + bv;
        r1.z = lo32(acc[i][3]) + bv; r1.w = hi32(acc[i][3]) + bv;
        *(float4*)(op + (tp << 2)) = r0;
        *(float4*)(op + 64 + (tp << 2)) = r1;
    }
}

// ---------------------------------------------------------------------------
// Kernel 3: GroupNorm statistics. One CTA per (b,g): 16ch x 4096px = 64K vals.
// Deterministic tree reduction (no atomics).
// ---------------------------------------------------------------------------
__global__ void k_stats() {
    int bg = blockIdx.x;  // 64
    const float4* ptr = (const float4*)(g_conv + ((size_t)bg << 16));
    float s = 0.f, ss = 0.f;
    for (int i = threadIdx.x; i < 16384; i += 256) {
        float4 v = ptr[i];
        s += v.x + v.y + v.z + v.w;
        ss += v.x * v.x + v.y * v.y + v.z * v.z + v.w * v.w;
    }
    __shared__ float sh[512];
    sh[threadIdx.x] = s;
    sh[256 + threadIdx.x] = ss;
    __syncthreads();
    for (int st = 128; st > 0; st >>= 1) {
        if (threadIdx.x < st) {
            sh[threadIdx.x] += sh[threadIdx.x + st];
            sh[256 + threadIdx.x] += sh[256 + threadIdx.x + st];
        }
        __syncthreads();
    }
    if (threadIdx.x == 0) {
        float mu = sh[0] * (1.f / 65536.f);
        float var = sh[256] * (1.f / 65536.f) - mu * mu;
        g_mu[bg] = mu;
        g_rs[bg] = rsqrtf(var + 1e-5f);
    }
}

// ---------------------------------------------------------------------------
// Kernel 4: normalize + affine -> d_out.  1,048,576 float4s.
// ---------------------------------------------------------------------------
__global__ void k_norm(const float* __restrict__ gamma,
                       const float* __restrict__ beta,
                       float* __restrict__ out) {
    int i = blockIdx.x * 256 + threadIdx.x;
    float4 v = ((const float4*)g_conv)[i];
    int bc = i >> 10;
    int c = bc & 255, b = bc >> 8;
    int bg = b * 16 + (c >> 4);
    float sc = g_rs[bg] * gamma[c];
    float sh = beta[c] - g_mu[bg] * sc;
    v.x = v.x * sc + sh;
    v.y = v.y * sc + sh;
    v.z = v.z * sc + sh;
    v.w = v.w * sc + sh;
    ((float4*)out)[i] = v;
}

// ---------------------------------------------------------------------------
extern "C" void kernel_launch(void* const* d_in, const int* in_sizes, int n_in,
                              void* d_out, int out_size) {
    // Identify uniquely-sized inputs by element count; the three 256-vectors
    // keep their metadata order (bias, gamma, beta).
    const float* x = nullptr;
    const float* w_off = nullptr;
    const float* b_off = nullptr;
    const float* weight = nullptr;
    const float* v256[3] = {nullptr, nullptr, nullptr};
    int n256 = 0;
    for (int i = 0; i < n_in; i++) {
        int s = in_sizes[i];
        const float* ptr = (const float*)d_in[i];
        if (s == 4194304) x = ptr;
        else if (s == 62208) w_off = ptr;
        else if (s == 27) b_off = ptr;
        else if (s == 589824) weight = ptr;
        else if (s == 256 && n256 < 3) v256[n256++] = ptr;
    }
    const float* bias  = v256[0];
    const float* gamma = v256[1];
    const float* beta  = v256[2];
    float* out = (float*)d_out;

    k_transpose<<<256, 256>>>(weight);
    k_offset<<<256, 576>>>(x, w_off, b_off);
    k_main<<<128, 512>>>(x, bias);
    k_stats<<<64, 256>>>();
    k_norm<<<4096, 256>>>(gamma, beta, out);
}

// round 6
// speedup vs baseline: 1.5603x; 1.5603x over previous
#include <cuda_runtime.h>
#include <cuda_bf16.h>
#include <cstdint>

// ---------------------------------------------------------------------------
// DCNv2 + GroupNorm16.  B=4, Cin=Cout=256, H=W=64, K=3, s=1, p=1, g=16.
// Main conv: warp-level mma.sync (HMMA) bf16 split-precision (3-term hi/lo)
// implicit GEMM. NOTE: harness compiles via compute_103 (no 'a'), so only
// baseline PTX features (mma.sync / ldmatrix / cp.async) are usable.
// ---------------------------------------------------------------------------

// ---- device-global scratch (no allocations allowed) -----------------------
__device__ int           g_midx[4 * 9 * 4096 * 4];   // bilinear corner idx
__device__ float         g_mw[4 * 9 * 4096 * 4];     // corner weight * mask
__device__ float         g_xT[4 * 4096 * 256];       // x transposed to NHWC
__device__ __nv_bfloat16 g_wBhi[72 * 256 * 32];      // weight hi [chunk][o][k]
__device__ __nv_bfloat16 g_wBlo[72 * 256 * 32];      // weight lo residual
__device__ float         g_conv[4 * 256 * 4096];     // conv out (pre-GN)
__device__ float         g_mu[64];
__device__ float         g_rs[64];

// ---- PTX helpers ----------------------------------------------------------
__device__ __forceinline__ unsigned smem_u32(const void* p) {
    unsigned a;
    asm("{ .reg .u64 t; cvta.to.shared.u64 t, %1; cvt.u32.u64 %0, t; }"
        : "=r"(a) : "l"(p));
    return a;
}
__device__ __forceinline__ unsigned pack_bf16x2(float lo, float hi) {
    unsigned r;
    asm("cvt.rn.bf16x2.f32 %0, %1, %2;" : "=r"(r) : "f"(hi), "f"(lo));
    return r;
}
#define CP16(s, g) asm volatile("cp.async.cg.shared.global [%0], [%1], 16;" :: "r"(s), "l"(g) : "memory")
#define CP_COMMIT() asm volatile("cp.async.commit_group;" ::: "memory")
#define CP_WAIT0()  asm volatile("cp.async.wait_group 0;" ::: "memory")

#define LDSM4(r, addr)                                                        \
    asm volatile("ldmatrix.sync.aligned.m8n8.x4.shared.b16 {%0,%1,%2,%3}, [%4];" \
                 : "=r"((r)[0]), "=r"((r)[1]), "=r"((r)[2]), "=r"((r)[3])     \
                 : "r"(addr))

#define MMA(ap, a, b0, b1)                                                    \
    asm volatile("mma.sync.aligned.m16n8k16.row.col.f32.bf16.bf16.f32 "       \
                 "{%0,%1,%2,%3}, {%4,%5,%6,%7}, {%8,%9}, {%0,%1,%2,%3};"      \
                 : "+f"((ap)[0]), "+f"((ap)[1]), "+f"((ap)[2]), "+f"((ap)[3]) \
                 : "r"((a)[0]), "r"((a)[1]), "r"((a)[2]), "r"((a)[3]),        \
                   "r"(b0), "r"(b1))

// ---------------------------------------------------------------------------
// Kernel: x NCHW -> NHWC transpose (for coalesced channel gathers)
// ---------------------------------------------------------------------------
__global__ void k_xT(const float* __restrict__ x) {
    __shared__ float t[32][33];
    int bx = blockIdx.x;                    // 4096 = b(4) * cblk(8) * pxblk(128)
    int pxb = bx & 127, cb = (bx >> 7) & 7, b = bx >> 10;
    int tx = threadIdx.x & 31, ty = threadIdx.x >> 5;   // 32 x 8
#pragma unroll
    for (int i = 0; i < 4; i++) {
        int c = cb * 32 + ty + i * 8;
        t[ty + i * 8][tx] = x[(((size_t)(b * 256 + c)) << 12) + pxb * 32 + tx];
    }
    __syncthreads();
#pragma unroll
    for (int i = 0; i < 4; i++) {
        int px = pxb * 32 + ty + i * 8;
        g_xT[(((size_t)b << 12) + px) * 256 + cb * 32 + tx] = t[tx][ty + i * 8];
    }
}

// ---------------------------------------------------------------------------
// Kernel: weight [O][C][3][3] -> per-chunk bf16 hi/lo, [ci][o][k32].
// chunk ci = tap*8 + cb;  channel = cb*32 + k;  tap = ky*3+kx.
// ---------------------------------------------------------------------------
__global__ void k_prepW(const float* __restrict__ w) {
    int o = blockIdx.x;
    for (int idx = threadIdx.x; idx < 2304; idx += 256) {
        int ci = idx >> 5, k = idx & 31;
        int tap = ci >> 3, c = ((ci & 7) << 5) + k;
        float v = w[o * 2304 + c * 9 + tap];
        __nv_bfloat16 h = __float2bfloat16(v);
        float l = v - __bfloat162float(h);
        size_t dst = (size_t)ci * 8192 + o * 32 + k;
        g_wBhi[dst] = h;
        g_wBlo[dst] = __float2bfloat16(l);
    }
}

// ---------------------------------------------------------------------------
// Kernel: offset conv (27 ch) fused with bilinear-meta generation
// ---------------------------------------------------------------------------
__global__ __launch_bounds__(576) void k_offset(const float* __restrict__ x,
                                                const float* __restrict__ wof,
                                                const float* __restrict__ bof) {
    __shared__ float xs[8][3][68];
    __shared__ float wsm[8][27][9];
    int b = blockIdx.x >> 6, h = blockIdx.x & 63;
    int tid = threadIdx.x;
    int k = tid / 64, p = tid & 63;
    float a0 = 0.f, a1 = 0.f, a2 = 0.f;

    for (int c0 = 0; c0 < 256; c0 += 8) {
        for (int i = tid; i < 8 * 3 * 66; i += 576) {
            int c = i / 198, r = i - c * 198;
            int row = r / 66, col = r - row * 66 - 1;
            int y = h - 1 + row;
            float v = 0.f;
            if (y >= 0 && y < 64 && col >= 0 && col < 64)
                v = x[(((b * 256 + c0 + c) * 64) + y) * 64 + col];
            xs[c][row][col + 1] = v;
        }
        for (int i = tid; i < 1944; i += 576) {
            int oc = i / 72, r = i - oc * 72;
            int c = r / 9, j = r - c * 9;
            wsm[c][oc][j] = wof[oc * 2304 + c0 * 9 + r];
        }
        __syncthreads();
#pragma unroll
        for (int c = 0; c < 8; c++) {
            float w0[9], w1[9], w2[9];
#pragma unroll
            for (int j = 0; j < 9; j++) {
                w0[j] = wsm[c][k][j];
                w1[j] = wsm[c][k + 9][j];
                w2[j] = wsm[c][k + 18][j];
            }
#pragma unroll
            for (int j = 0; j < 9; j++) {
                float xv = xs[c][j / 3][p + (j - (j / 3) * 3)];
                a0 = fmaf(xv, w0[j], a0);
                a1 = fmaf(xv, w1[j], a1);
                a2 = fmaf(xv, w2[j], a2);
            }
        }
        __syncthreads();
    }
    a0 += bof[k]; a1 += bof[k + 9]; a2 += bof[k + 18];
    float m = 1.f / (1.f + __expf(-a2));
    float py = (float)(h - 1 + k / 3) + a0;
    float px = (float)(p - 1 + (k - (k / 3) * 3)) + a1;
    float y0f = floorf(py), x0f = floorf(px);
    float wy1 = py - y0f, wx1 = px - x0f;
    int y0 = (int)y0f, x0 = (int)x0f;
    size_t base = ((size_t)(b * 9 + k) * 4096 + (size_t)(h * 64 + p)) * 4;
#pragma unroll
    for (int j = 0; j < 4; j++) {
        int dy = j >> 1, dx = j & 1;
        int yy = y0 + dy, xx = x0 + dx;
        float wv = (dy ? wy1 : 1.f - wy1) * (dx ? wx1 : 1.f - wx1);
        bool valid = (yy >= 0) && (yy < 64) && (xx >= 0) && (xx < 64);
        int yc = min(max(yy, 0), 63), xc = min(max(xx, 0), 63);
        g_midx[base + j] = yc * 64 + xc;
        g_mw[base + j] = valid ? wv * m : 0.f;
    }
}

// ---------------------------------------------------------------------------
// Main: fused sampling + HMMA bf16 split GEMM.
// Grid 128 = (b, 32 px-tiles of 128). 512 threads = 16 warps (4 M x 4 N).
// Warp tile 32(M) x 64(N); K chunks of 32 (72 chunks), double-buffered smem.
// SMEM: A[buf][hi/lo]: 128 rows x 80B = 10240 each (40960 total)
//       B[buf][hi/lo]: 256 rows x 80B = 20480 each (81920 total) = 122880 B
// ---------------------------------------------------------------------------
#define SA(buf, term) ((buf) * 20480 + (term) * 10240)
#define SB(buf, term) (40960 + (buf) * 40960 + (term) * 20480)
#define SMEM_TOTAL 122880

__global__ __launch_bounds__(512, 1) void k_mainTC(const float* __restrict__ bias) {
    extern __shared__ char sm[];
    unsigned smb = smem_u32(sm);
    int tid = threadIdx.x, lane = tid & 31, wid = tid >> 5;
    int wm = wid & 3, wn = wid >> 2;
    int b = blockIdx.x >> 5;
    int p0 = (blockIdx.x & 31) << 7;

    float acc[64];
#pragma unroll
    for (int i = 0; i < 64; i++) acc[i] = 0.f;

    // A-gather statics: thread = (px, oct of 8 channels)
    int px = tid >> 2, oct = tid & 3;
    const float* xb = g_xT + ((size_t)b << 20);
    int4 mi;
    float4 mw;
    float sampA[8];

    // B cp.async statics: thread = (term, o-row)
    int term = tid >> 8, orow = tid & 255;
    const __nv_bfloat16* wsrc = term ? g_wBlo : g_wBhi;

    // ldmatrix per-lane offsets
    unsigned aoff = (unsigned)((lane & 15) * 80 + (lane >> 4) * 16);
    unsigned boff = (unsigned)((lane & 7) * 80 + ((lane >> 3) & 1) * 16 +
                               (lane >> 4) * 640);

    // ---- prologue: meta tap0, gather chunk0, issue B chunk0 ----
    {
        size_t mb = ((((size_t)(b * 9 + 0)) << 12) + (p0 + px)) << 2;
        mi = *(const int4*)(g_midx + mb);
        mw = *(const float4*)(g_mw + mb);
    }
    {
        const float* base = xb + oct * 8;   // chunk0: c0 = 0
        const float* pp = base + ((size_t)mi.x << 8);
        float4 v0 = *(const float4*)pp, v1 = *(const float4*)(pp + 4);
        sampA[0] = mw.x * v0.x; sampA[1] = mw.x * v0.y;
        sampA[2] = mw.x * v0.z; sampA[3] = mw.x * v0.w;
        sampA[4] = mw.x * v1.x; sampA[5] = mw.x * v1.y;
        sampA[6] = mw.x * v1.z; sampA[7] = mw.x * v1.w;
        pp = base + ((size_t)mi.y << 8);
        v0 = *(const float4*)pp; v1 = *(const float4*)(pp + 4);
        sampA[0] = fmaf(mw.y, v0.x, sampA[0]); sampA[1] = fmaf(mw.y, v0.y, sampA[1]);
        sampA[2] = fmaf(mw.y, v0.z, sampA[2]); sampA[3] = fmaf(mw.y, v0.w, sampA[3]);
        sampA[4] = fmaf(mw.y, v1.x, sampA[4]); sampA[5] = fmaf(mw.y, v1.y, sampA[5]);
        sampA[6] = fmaf(mw.y, v1.z, sampA[6]); sampA[7] = fmaf(mw.y, v1.w, sampA[7]);
        pp = base + ((size_t)mi.z << 8);
        v0 = *(const float4*)pp; v1 = *(const float4*)(pp + 4);
        sampA[0] = fmaf(mw.z, v0.x, sampA[0]); sampA[1] = fmaf(mw.z, v0.y, sampA[1]);
        sampA[2] = fmaf(mw.z, v0.z, sampA[2]); sampA[3] = fmaf(mw.z, v0.w, sampA[3]);
        sampA[4] = fmaf(mw.z, v1.x, sampA[4]); sampA[5] = fmaf(mw.z, v1.y, sampA[5]);
        sampA[6] = fmaf(mw.z, v1.z, sampA[6]); sampA[7] = fmaf(mw.z, v1.w, sampA[7]);
        pp = base + ((size_t)mi.w << 8);
        v0 = *(const float4*)pp; v1 = *(const float4*)(pp + 4);
        sampA[0] = fmaf(mw.w, v0.x, sampA[0]); sampA[1] = fmaf(mw.w, v0.y, sampA[1]);
        sampA[2] = fmaf(mw.w, v0.z, sampA[2]); sampA[3] = fmaf(mw.w, v0.w, sampA[3]);
        sampA[4] = fmaf(mw.w, v1.x, sampA[4]); sampA[5] = fmaf(mw.w, v1.y, sampA[5]);
        sampA[6] = fmaf(mw.w, v1.z, sampA[6]); sampA[7] = fmaf(mw.w, v1.w, sampA[7]);
    }
    {
        const __nv_bfloat16* g = wsrc + (size_t)orow * 32;   // ci = 0
        unsigned s = smb + SB(0, term) + orow * 80;
        CP16(s, g); CP16(s + 16, g + 8); CP16(s + 32, g + 16); CP16(s + 48, g + 24);
        CP_COMMIT();
    }

#pragma unroll 1
    for (int ci = 0; ci < 72; ci++) {
        int buf = ci & 1;
        // ---- 1. split & store A(ci) from sampA ----
        {
            unsigned hp[4], lp[4];
#pragma unroll
            for (int j = 0; j < 4; j++) {
                float s0 = sampA[2 * j], s1 = sampA[2 * j + 1];
                __nv_bfloat16 h0 = __float2bfloat16(s0);
                __nv_bfloat16 h1 = __float2bfloat16(s1);
                hp[j] = ((unsigned)__bfloat16_as_ushort(h1) << 16) |
                        (unsigned)__bfloat16_as_ushort(h0);
                lp[j] = pack_bf16x2(s0 - __bfloat162float(h0),
                                    s1 - __bfloat162float(h1));
            }
            unsigned ao = (unsigned)(px * 80 + oct * 16);
            *(uint4*)(sm + SA(buf, 0) + ao) = make_uint4(hp[0], hp[1], hp[2], hp[3]);
            *(uint4*)(sm + SA(buf, 1) + ao) = make_uint4(lp[0], lp[1], lp[2], lp[3]);
        }
        CP_WAIT0();        // B(ci) landed
        __syncthreads();

        // ---- 2. prefetch next chunk (A gather -> regs, B cp.async) ----
        if (ci < 71) {
            int cn = ci + 1;
            if ((cn & 7) == 0) {
                size_t mb = ((((size_t)(b * 9 + (cn >> 3))) << 12) + (p0 + px)) << 2;
                mi = *(const int4*)(g_midx + mb);
                mw = *(const float4*)(g_mw + mb);
            }
            const float* base = xb + ((cn & 7) << 5) + oct * 8;
            const float* pp = base + ((size_t)mi.x << 8);
            float4 v0 = *(const float4*)pp, v1 = *(const float4*)(pp + 4);
            sampA[0] = mw.x * v0.x; sampA[1] = mw.x * v0.y;
            sampA[2] = mw.x * v0.z; sampA[3] = mw.x * v0.w;
            sampA[4] = mw.x * v1.x; sampA[5] = mw.x * v1.y;
            sampA[6] = mw.x * v1.z; sampA[7] = mw.x * v1.w;
            pp = base + ((size_t)mi.y << 8);
            v0 = *(const float4*)pp; v1 = *(const float4*)(pp + 4);
            sampA[0] = fmaf(mw.y, v0.x, sampA[0]); sampA[1] = fmaf(mw.y, v0.y, sampA[1]);
            sampA[2] = fmaf(mw.y, v0.z, sampA[2]); sampA[3] = fmaf(mw.y, v0.w, sampA[3]);
            sampA[4] = fmaf(mw.y, v1.x, sampA[4]); sampA[5] = fmaf(mw.y, v1.y, sampA[5]);
            sampA[6] = fmaf(mw.y, v1.z, sampA[6]); sampA[7] = fmaf(mw.y, v1.w, sampA[7]);
            pp = base + ((size_t)mi.z << 8);
            v0 = *(const float4*)pp; v1 = *(const float4*)(pp + 4);
            sampA[0] = fmaf(mw.z, v0.x, sampA[0]); sampA[1] = fmaf(mw.z, v0.y, sampA[1]);
            sampA[2] = fmaf(mw.z, v0.z, sampA[2]); sampA[3] = fmaf(mw.z, v0.w, sampA[3]);
            sampA[4] = fmaf(mw.z, v1.x, sampA[4]); sampA[5] = fmaf(mw.z, v1.y, sampA[5]);
            sampA[6] = fmaf(mw.z, v1.z, sampA[6]); sampA[7] = fmaf(mw.z, v1.w, sampA[7]);
            pp = base + ((size_t)mi.w << 8);
            v0 = *(const float4*)pp; v1 = *(const float4*)(pp + 4);
            sampA[0] = fmaf(mw.w, v0.x, sampA[0]); sampA[1] = fmaf(mw.w, v0.y, sampA[1]);
            sampA[2] = fmaf(mw.w, v0.z, sampA[2]); sampA[3] = fmaf(mw.w, v0.w, sampA[3]);
            sampA[4] = fmaf(mw.w, v1.x, sampA[4]); sampA[5] = fmaf(mw.w, v1.y, sampA[5]);
            sampA[6] = fmaf(mw.w, v1.z, sampA[6]); sampA[7] = fmaf(mw.w, v1.w, sampA[7]);

            const __nv_bfloat16* g = wsrc + (size_t)cn * 8192 + orow * 32;
            unsigned s = smb + SB(buf ^ 1, term) + orow * 80;
            CP16(s, g); CP16(s + 16, g + 8); CP16(s + 32, g + 16); CP16(s + 48, g + 24);
            CP_COMMIT();
        }

        // ---- 3. MMA over buf: 2 ksteps x (4 A-ldsm + 4 ntp x (2 B-ldsm + 12 mma))
#pragma unroll
        for (int ks = 0; ks < 2; ks++) {
            unsigned ab = smb + (unsigned)(buf * 20480 + wm * 2560 + ks * 32) + aoff;
            unsigned ah0[4], ah1[4], al0[4], al1[4];
            LDSM4(ah0, ab);
            LDSM4(ah1, ab + 1280);
            LDSM4(al0, ab + 10240);
            LDSM4(al1, ab + 11520);
            unsigned bb = smb + (unsigned)(40960 + buf * 40960 + wn * 5120 + ks * 32) + boff;
#pragma unroll
            for (int ntp = 0; ntp < 4; ntp++) {
                unsigned bh[4], bl[4];
                LDSM4(bh, bb + ntp * 1280);
                LDSM4(bl, bb + 20480 + ntp * 1280);
                float* a00 = &acc[(0 * 8 + ntp * 2) * 4];
                float* a01 = &acc[(0 * 8 + ntp * 2 + 1) * 4];
                float* a10 = &acc[(1 * 8 + ntp * 2) * 4];
                float* a11 = &acc[(1 * 8 + ntp * 2 + 1) * 4];
                MMA(a00, ah0, bh[0], bh[1]);
                MMA(a01, ah0, bh[2], bh[3]);
                MMA(a10, ah1, bh[0], bh[1]);
                MMA(a11, ah1, bh[2], bh[3]);
                MMA(a00, ah0, bl[0], bl[1]);
                MMA(a01, ah0, bl[2], bl[3]);
                MMA(a10, ah1, bl[0], bl[1]);
                MMA(a11, ah1, bl[2], bl[3]);
                MMA(a00, al0, bh[0], bh[1]);
                MMA(a01, al0, bh[2], bh[3]);
                MMA(a10, al1, bh[0], bh[1]);
                MMA(a11, al1, bh[2], bh[3]);
            }
        }
        __syncthreads();
    }

    // ---- epilogue: acc -> g_conv[b][o][px] with bias ----
    int pxb = p0 + wm * 32 + (lane >> 2);
#pragma unroll
    for (int mt = 0; mt < 2; mt++) {
#pragma unroll
        for (int nt = 0; nt < 8; nt++) {
            float* ap = &acc[(mt * 8 + nt) * 4];
            int o = wn * 64 + nt * 8 + (lane & 3) * 2;
            float bv0 = __ldg(bias + o), bv1 = __ldg(bias + o + 1);
            int pxm = pxb + mt * 16;
            size_t r0 = (((size_t)(b * 256 + o)) << 12) + pxm;
            size_t r1 = r0 + 4096;   // o+1
            g_conv[r0] = ap[0] + bv0;
            g_conv[r1] = ap[1] + bv1;
            g_conv[r0 + 8] = ap[2] + bv0;
            g_conv[r1 + 8] = ap[3] + bv1;
        }
    }
}

// ---------------------------------------------------------------------------
// GroupNorm statistics
// ---------------------------------------------------------------------------
__global__ void k_stats() {
    int bg = blockIdx.x;
    const float4* ptr = (const float4*)(g_conv + ((size_t)bg << 16));
    float s = 0.f, ss = 0.f;
    for (int i = threadIdx.x; i < 16384; i += 256) {
        float4 v = ptr[i];
        s += v.x + v.y + v.z + v.w;
        ss += v.x * v.x + v.y * v.y + v.z * v.z + v.w * v.w;
    }
    __shared__ float sh[512];
    sh[threadIdx.x] = s;
    sh[256 + threadIdx.x] = ss;
    __syncthreads();
    for (int st = 128; st > 0; st >>= 1) {
        if (threadIdx.x < st) {
            sh[threadIdx.x] += sh[threadIdx.x + st];
            sh[256 + threadIdx.x] += sh[256 + threadIdx.x + st];
        }
        __syncthreads();
    }
    if (threadIdx.x == 0) {
        float mu = sh[0] * (1.f / 65536.f);
        float var = sh[256] * (1.f / 65536.f) - mu * mu;
        g_mu[bg] = mu;
        g_rs[bg] = rsqrtf(var + 1e-5f);
    }
}

// ---------------------------------------------------------------------------
// Normalize + affine -> d_out
// ---------------------------------------------------------------------------
__global__ void k_norm(const float* __restrict__ gamma,
                       const float* __restrict__ beta,
                       float* __restrict__ out) {
    int i = blockIdx.x * 256 + threadIdx.x;
    float4 v = ((const float4*)g_conv)[i];
    int bc = i >> 10;
    int c = bc & 255, b = bc >> 8;
    int bg = b * 16 + (c >> 4);
    float sc = g_rs[bg] * gamma[c];
    float sh = beta[c] - g_mu[bg] * sc;
    v.x = v.x * sc + sh;
    v.y = v.y * sc + sh;
    v.z = v.z * sc + sh;
    v.w = v.w * sc + sh;
    ((float4*)out)[i] = v;
}

// ---------------------------------------------------------------------------
extern "C" void kernel_launch(void* const* d_in, const int* in_sizes, int n_in,
                              void* d_out, int out_size) {
    const float* x = nullptr;
    const float* w_off = nullptr;
    const float* b_off = nullptr;
    const float* weight = nullptr;
    const float* v256[3] = {nullptr, nullptr, nullptr};
    int n256 = 0;
    for (int i = 0; i < n_in; i++) {
        int s = in_sizes[i];
        const float* ptr = (const float*)d_in[i];
        if (s == 4194304) x = ptr;
        else if (s == 62208) w_off = ptr;
        else if (s == 27) b_off = ptr;
        else if (s == 589824) weight = ptr;
        else if (s == 256 && n256 < 3) v256[n256++] = ptr;
    }
    const float* bias  = v256[0];
    const float* gamma = v256[1];
    const float* beta  = v256[2];
    float* out = (float*)d_out;

    cudaFuncSetAttribute(k_mainTC, cudaFuncAttributeMaxDynamicSharedMemorySize,
                         SMEM_TOTAL);

    k_xT<<<4096, 256>>>(x);
    k_prepW<<<256, 256>>>(weight);
    k_offset<<<256, 576>>>(x, w_off, b_off);
    k_mainTC<<<128, 512, SMEM_TOTAL>>>(bias);
    k_stats<<<64, 256>>>();
    k_norm<<<4096, 256>>>(gamma, beta, out);
}

// round 8
// speedup vs baseline: 2.7335x; 1.7520x over previous
#include <cuda_runtime.h>
#include <cuda_fp16.h>
#include <cstdint>

// ---------------------------------------------------------------------------
// DCNv2 + GroupNorm16.  B=4, Cin=Cout=256, H=W=64, K=3, s=1, p=1, g=16.
// Main conv: HMMA fp16, A split hi/lo (2-term), B single fp16.
// Offset conv: HMMA fp16 GEMM (im2col from NHWC x) + fused bilinear meta.
// Harness compiles via compute_103 (no 'a') -> baseline PTX only.
// ---------------------------------------------------------------------------

// ---- device-global scratch (no allocations allowed) -----------------------
__device__ int    g_midx[4 * 9 * 4096 * 4];   // bilinear corner idx
__device__ float  g_mw[4 * 9 * 4096 * 4];     // corner weight * mask
__device__ float  g_xT[4 * 4096 * 256];       // x transposed to NHWC
__device__ __half g_wF16[72 * 256 * 32];      // main weight fp16 [ci][o][k]
__device__ __half g_wOf[72 * 32 * 32];        // offset weight fp16 [ci][o32][k]
__device__ float  g_conv[4 * 256 * 4096];     // conv out (pre-GN)
__device__ float  g_mu[64];
__device__ float  g_rs[64];

// ---- PTX helpers ----------------------------------------------------------
__device__ __forceinline__ unsigned smem_u32(const void* p) {
    unsigned a;
    asm("{ .reg .u64 t; cvta.to.shared.u64 t, %1; cvt.u32.u64 %0, t; }"
        : "=r"(a) : "l"(p));
    return a;
}
#define CP16(s, g) asm volatile("cp.async.cg.shared.global [%0], [%1], 16;" :: "r"(s), "l"(g) : "memory")
#define CP_COMMIT() asm volatile("cp.async.commit_group;" ::: "memory")
#define CP_WAIT0()  asm volatile("cp.async.wait_group 0;" ::: "memory")

#define LDSM4(r, addr)                                                        \
    asm volatile("ldmatrix.sync.aligned.m8n8.x4.shared.b16 {%0,%1,%2,%3}, [%4];" \
                 : "=r"((r)[0]), "=r"((r)[1]), "=r"((r)[2]), "=r"((r)[3])     \
                 : "r"(addr))

#define MMA(ap, a, b0, b1)                                                    \
    asm volatile("mma.sync.aligned.m16n8k16.row.col.f32.f16.f16.f32 "         \
                 "{%0,%1,%2,%3}, {%4,%5,%6,%7}, {%8,%9}, {%0,%1,%2,%3};"      \
                 : "+f"((ap)[0]), "+f"((ap)[1]), "+f"((ap)[2]), "+f"((ap)[3]) \
                 : "r"((a)[0]), "r"((a)[1]), "r"((a)[2]), "r"((a)[3]),        \
                   "r"(b0), "r"(b1))

__device__ __forceinline__ unsigned pack_h2(float s0, float s1) {
    __half2 h = __floats2half2_rn(s0, s1);
    return *reinterpret_cast<unsigned*>(&h);
}
__device__ __forceinline__ void split_pair(float s0, float s1,
                                           unsigned& hp, unsigned& lp) {
    __half h0 = __float2half(s0), h1 = __float2half(s1);
    __half2 hh = __halves2half2(h0, h1);
    hp = *reinterpret_cast<unsigned*>(&hh);
    lp = pack_h2(s0 - __half2float(h0), s1 - __half2float(h1));
}

// ---------------------------------------------------------------------------
// x NCHW -> NHWC transpose
// ---------------------------------------------------------------------------
__global__ void k_xT(const float* __restrict__ x) {
    __shared__ float t[32][33];
    int bx = blockIdx.x;                    // 4096 = b(4) * cblk(8) * pxblk(128)
    int pxb = bx & 127, cb = (bx >> 7) & 7, b = bx >> 10;
    int tx = threadIdx.x & 31, ty = threadIdx.x >> 5;
#pragma unroll
    for (int i = 0; i < 4; i++) {
        int c = cb * 32 + ty + i * 8;
        t[ty + i * 8][tx] = x[(((size_t)(b * 256 + c)) << 12) + pxb * 32 + tx];
    }
    __syncthreads();
#pragma unroll
    for (int i = 0; i < 4; i++) {
        int px = pxb * 32 + ty + i * 8;
        g_xT[(((size_t)b << 12) + px) * 256 + cb * 32 + tx] = t[tx][ty + i * 8];
    }
}

// ---------------------------------------------------------------------------
// main weight [O][C][3][3] -> fp16 [ci][o][k32];  ci = tap*8+cb, c = cb*32+k
// ---------------------------------------------------------------------------
__global__ void k_prepW(const float* __restrict__ w) {
    int o = blockIdx.x;
    for (int idx = threadIdx.x; idx < 2304; idx += 256) {
        int ci = idx >> 5, k = idx & 31;
        int tap = ci >> 3, c = ((ci & 7) << 5) + k;
        g_wF16[(size_t)ci * 8192 + o * 32 + k] =
            __float2half(w[o * 2304 + c * 9 + tap]);
    }
}

// ---------------------------------------------------------------------------
// offset weight [27][C][3][3] -> fp16 [ci][o(32, >=27 zero)][k32]
// ---------------------------------------------------------------------------
__global__ void k_offW(const float* __restrict__ wof) {
    int ci = blockIdx.x;                    // 72
    int tap = ci >> 3, cb = ci & 7;
    for (int i = threadIdx.x; i < 1024; i += 256) {
        int o = i >> 5, k = i & 31;
        int c = (cb << 5) + k;
        float v = (o < 27) ? wof[o * 2304 + c * 9 + tap] : 0.f;
        g_wOf[ci * 1024 + i] = __float2half(v);
    }
}

// ---------------------------------------------------------------------------
// Offset conv as HMMA GEMM + fused bilinear-meta epilogue.
// Grid 128 = (b, 32 px-tiles of 128). 256 threads = 8 warps, warp tile 16x32.
// A: im2col rows of g_xT (fp16 hi/lo split), B: g_wOf (fp16 single).
// SMEM static 46080: A[buf][term] 128x80 (=10240), B[buf] 32x80 (=2560).
// ---------------------------------------------------------------------------
#define OGA(buf, term) ((buf) * 20480 + (term) * 10240)
#define OGB(buf)       (40960 + (buf) * 2560)

__global__ __launch_bounds__(256) void k_offGemm(const float* __restrict__ bof) {
    __shared__ char sm[46080];
    unsigned smb = smem_u32(sm);
    int tid = threadIdx.x, lane = tid & 31, wm = tid >> 5;
    int b = blockIdx.x >> 5;
    int p0 = (blockIdx.x & 31) << 7;

    float acc[4][4];
#pragma unroll
    for (int i = 0; i < 4; i++)
#pragma unroll
        for (int j = 0; j < 4; j++) acc[i][j] = 0.f;

    const float* xb = g_xT + ((size_t)b << 20);
    int r = tid & 127, half = tid >> 7;
    int gp = p0 + r, h = gp >> 6, w = gp & 63;

    unsigned aoff = (unsigned)((lane & 15) * 80 + (lane >> 4) * 16);
    unsigned boff = (unsigned)((lane & 7) * 80 + ((lane >> 3) & 1) * 16 +
                               (lane >> 4) * 640);

    float4 v0, v1, v2, v3;
    auto loadA = [&](int ci) {
        int tap = ci >> 3, cb = ci & 7;
        int py = h + tap / 3 - 1, px = w + tap % 3 - 1;
        if (py >= 0 && py < 64 && px >= 0 && px < 64) {
            const float* s = xb + (((size_t)(py * 64 + px)) << 8) + (cb << 5) +
                             (half << 4);
            v0 = *(const float4*)s;       v1 = *(const float4*)(s + 4);
            v2 = *(const float4*)(s + 8); v3 = *(const float4*)(s + 12);
        } else {
            v0 = v1 = v2 = v3 = make_float4(0.f, 0.f, 0.f, 0.f);
        }
    };
    auto storeA = [&](int buf) {
        unsigned hp[8], lp[8];
        split_pair(v0.x, v0.y, hp[0], lp[0]); split_pair(v0.z, v0.w, hp[1], lp[1]);
        split_pair(v1.x, v1.y, hp[2], lp[2]); split_pair(v1.z, v1.w, hp[3], lp[3]);
        split_pair(v2.x, v2.y, hp[4], lp[4]); split_pair(v2.z, v2.w, hp[5], lp[5]);
        split_pair(v3.x, v3.y, hp[6], lp[6]); split_pair(v3.z, v3.w, hp[7], lp[7]);
        unsigned ao = (unsigned)(r * 80 + half * 32);
        *(uint4*)(sm + OGA(buf, 0) + ao) = make_uint4(hp[0], hp[1], hp[2], hp[3]);
        *(uint4*)(sm + OGA(buf, 0) + ao + 16) = make_uint4(hp[4], hp[5], hp[6], hp[7]);
        *(uint4*)(sm + OGA(buf, 1) + ao) = make_uint4(lp[0], lp[1], lp[2], lp[3]);
        *(uint4*)(sm + OGA(buf, 1) + ao + 16) = make_uint4(lp[4], lp[5], lp[6], lp[7]);
    };
    auto loadB = [&](int ci, int buf) {
        if (tid < 128) {
            int row = tid >> 2, q = tid & 3;
            const __half* src = g_wOf + ci * 1024 + row * 32 + q * 8;
            CP16(smb + OGB(buf) + row * 80 + q * 16, src);
        }
        CP_COMMIT();
    };

    loadA(0);
    loadB(0, 0);

#pragma unroll 1
    for (int ci = 0; ci < 72; ci++) {
        int buf = ci & 1;
        storeA(buf);
        CP_WAIT0();
        __syncthreads();
        if (ci < 71) { loadA(ci + 1); loadB(ci + 1, buf ^ 1); }
        unsigned aB = smb + OGA(buf, 0) + (unsigned)(wm * 1280) + aoff;
        unsigned bB = smb + OGB(buf) + boff;
#pragma unroll
        for (int ks = 0; ks < 2; ks++) {
            unsigned ah[4], al[4];
            LDSM4(ah, aB + ks * 32);
            LDSM4(al, aB + 10240 + ks * 32);
#pragma unroll
            for (int ntp = 0; ntp < 2; ntp++) {
                unsigned bh[4];
                LDSM4(bh, bB + ntp * 1280 + ks * 32);
                MMA(acc[ntp * 2], ah, bh[0], bh[1]);
                MMA(acc[ntp * 2 + 1], ah, bh[2], bh[3]);
                MMA(acc[ntp * 2], al, bh[0], bh[1]);
                MMA(acc[ntp * 2 + 1], al, bh[2], bh[3]);
            }
        }
        __syncthreads();
    }

    // epilogue: acc -> smem om[128][36], then bilinear meta
    float* som = (float*)sm;
    {
        int row = wm * 16 + (lane >> 2);
        int col = (lane & 3) * 2;
#pragma unroll
        for (int nt = 0; nt < 4; nt++) {
            int c = nt * 8 + col;
            som[row * 36 + c] = acc[nt][0];
            som[row * 36 + c + 1] = acc[nt][1];
            som[(row + 8) * 36 + c] = acc[nt][2];
            som[(row + 8) * 36 + c + 1] = acc[nt][3];
        }
    }
    __syncthreads();
    for (int idx = tid; idx < 1152; idx += 256) {
        int px = idx / 9, k = idx - px * 9;
        float ay = som[px * 36 + k] + __ldg(bof + k);
        float ax = som[px * 36 + k + 9] + __ldg(bof + k + 9);
        float am = som[px * 36 + k + 18] + __ldg(bof + k + 18);
        float m = 1.f / (1.f + __expf(-am));
        int gp2 = p0 + px, hh = gp2 >> 6, ww = gp2 & 63;
        float py = (float)(hh + k / 3 - 1) + ay;
        float pxx = (float)(ww + (k - (k / 3) * 3) - 1) + ax;
        float y0f = floorf(py), x0f = floorf(pxx);
        float wy1 = py - y0f, wx1 = pxx - x0f;
        int y0 = (int)y0f, x0 = (int)x0f;
        size_t base = (((size_t)(b * 9 + k) << 12) + (size_t)gp2) * 4;
#pragma unroll
        for (int j = 0; j < 4; j++) {
            int dy = j >> 1, dx = j & 1;
            int yy = y0 + dy, xx = x0 + dx;
            float wv = (dy ? wy1 : 1.f - wy1) * (dx ? wx1 : 1.f - wx1);
            bool valid = (yy >= 0) && (yy < 64) && (xx >= 0) && (xx < 64);
            int yc = min(max(yy, 0), 63), xc = min(max(xx, 0), 63);
            g_midx[base + j] = yc * 64 + xc;
            g_mw[base + j] = valid ? wv * m : 0.f;
        }
    }
}

// ---------------------------------------------------------------------------
// Main: fused sampling + HMMA fp16 GEMM, A split (2 terms), B single.
// Grid 128 = (b, 32 px-tiles of 128). 512 threads = 16 warps (4M x 4N),
// warp tile 32x64, K chunks of 32 (72), double-buffered smem.
// SMEM: A[buf][term] 128x80 = 10240 each (40960); B[buf] 256x80 = 20480 each.
// ---------------------------------------------------------------------------
#define SA(buf, term) ((buf) * 20480 + (term) * 10240)
#define SB(buf) (40960 + (buf) * 20480)
#define SMEM_TOTAL 81920

__global__ __launch_bounds__(512, 1) void k_mainTC(const float* __restrict__ bias) {
    extern __shared__ char sm[];
    unsigned smb = smem_u32(sm);
    int tid = threadIdx.x, lane = tid & 31, wid = tid >> 5;
    int wm = wid & 3, wn = wid >> 2;
    int b = blockIdx.x >> 5;
    int p0 = (blockIdx.x & 31) << 7;

    float acc[64];
#pragma unroll
    for (int i = 0; i < 64; i++) acc[i] = 0.f;

    int px = tid >> 2, oct = tid & 3;
    const float* xb = g_xT + ((size_t)b << 20);
    int4 mi;
    float4 mw;
    float sampA[8];

    unsigned aoff = (unsigned)((lane & 15) * 80 + (lane >> 4) * 16);
    unsigned boff = (unsigned)((lane & 7) * 80 + ((lane >> 3) & 1) * 16 +
                               (lane >> 4) * 640);

    auto gather = [&](int cn) {
        const float* base = xb + ((cn & 7) << 5) + oct * 8;
        const float* pp = base + ((size_t)mi.x << 8);
        float4 u0 = *(const float4*)pp, u1 = *(const float4*)(pp + 4);
        sampA[0] = mw.x * u0.x; sampA[1] = mw.x * u0.y;
        sampA[2] = mw.x * u0.z; sampA[3] = mw.x * u0.w;
        sampA[4] = mw.x * u1.x; sampA[5] = mw.x * u1.y;
        sampA[6] = mw.x * u1.z; sampA[7] = mw.x * u1.w;
        pp = base + ((size_t)mi.y << 8);
        u0 = *(const float4*)pp; u1 = *(const float4*)(pp + 4);
        sampA[0] = fmaf(mw.y, u0.x, sampA[0]); sampA[1] = fmaf(mw.y, u0.y, sampA[1]);
        sampA[2] = fmaf(mw.y, u0.z, sampA[2]); sampA[3] = fmaf(mw.y, u0.w, sampA[3]);
        sampA[4] = fmaf(mw.y, u1.x, sampA[4]); sampA[5] = fmaf(mw.y, u1.y, sampA[5]);
        sampA[6] = fmaf(mw.y, u1.z, sampA[6]); sampA[7] = fmaf(mw.y, u1.w, sampA[7]);
        pp = base + ((size_t)mi.z << 8);
        u0 = *(const float4*)pp; u1 = *(const float4*)(pp + 4);
        sampA[0] = fmaf(mw.z, u0.x, sampA[0]); sampA[1] = fmaf(mw.z, u0.y, sampA[1]);
        sampA[2] = fmaf(mw.z, u0.z, sampA[2]); sampA[3] = fmaf(mw.z, u0.w, sampA[3]);
        sampA[4] = fmaf(mw.z, u1.x, sampA[4]); sampA[5] = fmaf(mw.z, u1.y, sampA[5]);
        sampA[6] = fmaf(mw.z, u1.z, sampA[6]); sampA[7] = fmaf(mw.z, u1.w, sampA[7]);
        pp = base + ((size_t)mi.w << 8);
        u0 = *(const float4*)pp; u1 = *(const float4*)(pp + 4);
        sampA[0] = fmaf(mw.w, u0.x, sampA[0]); sampA[1] = fmaf(mw.w, u0.y, sampA[1]);
        sampA[2] = fmaf(mw.w, u0.z, sampA[2]); sampA[3] = fmaf(mw.w, u0.w, sampA[3]);
        sampA[4] = fmaf(mw.w, u1.x, sampA[4]); sampA[5] = fmaf(mw.w, u1.y, sampA[5]);
        sampA[6] = fmaf(mw.w, u1.z, sampA[6]); sampA[7] = fmaf(mw.w, u1.w, sampA[7]);
    };
    auto loadB = [&](int ci, int buf) {
        if (tid < 256) {
            const __half* g = g_wF16 + (size_t)ci * 8192 + tid * 32;
            unsigned s = smb + SB(buf) + tid * 80;
            CP16(s, g); CP16(s + 16, g + 8);
            CP16(s + 32, g + 16); CP16(s + 48, g + 24);
        }
        CP_COMMIT();
    };

    // prologue: meta tap0, gather chunk0, B chunk0
    {
        size_t mb = ((((size_t)(b * 9)) << 12) + (p0 + px)) << 2;
        mi = *(const int4*)(g_midx + mb);
        mw = *(const float4*)(g_mw + mb);
    }
    gather(0);
    loadB(0, 0);

#pragma unroll 1
    for (int ci = 0; ci < 72; ci++) {
        int buf = ci & 1;
        // split & store A(ci)
        {
            unsigned hp[4], lp[4];
            split_pair(sampA[0], sampA[1], hp[0], lp[0]);
            split_pair(sampA[2], sampA[3], hp[1], lp[1]);
            split_pair(sampA[4], sampA[5], hp[2], lp[2]);
            split_pair(sampA[6], sampA[7], hp[3], lp[3]);
            unsigned ao = (unsigned)(px * 80 + oct * 16);
            *(uint4*)(sm + SA(buf, 0) + ao) = make_uint4(hp[0], hp[1], hp[2], hp[3]);
            *(uint4*)(sm + SA(buf, 1) + ao) = make_uint4(lp[0], lp[1], lp[2], lp[3]);
        }
        CP_WAIT0();
        __syncthreads();

        if (ci < 71) {
            int cn = ci + 1;
            if ((cn & 7) == 0) {
                size_t mb = ((((size_t)(b * 9 + (cn >> 3))) << 12) + (p0 + px)) << 2;
                mi = *(const int4*)(g_midx + mb);
                mw = *(const float4*)(g_mw + mb);
            }
            gather(cn);
            loadB(cn, buf ^ 1);
        }

        // MMA: 2 ksteps x (4 A-ldsm + 4 ntp x (1 B-ldsm + 8 mma))
#pragma unroll
        for (int ks = 0; ks < 2; ks++) {
            unsigned ab = smb + (unsigned)(buf * 20480 + wm * 2560 + ks * 32) + aoff;
            unsigned ah0[4], ah1[4], al0[4], al1[4];
            LDSM4(ah0, ab);
            LDSM4(ah1, ab + 1280);
            LDSM4(al0, ab + 10240);
            LDSM4(al1, ab + 11520);
            unsigned bb = smb + (unsigned)(40960 + buf * 20480 + wn * 5120 + ks * 32) + boff;
#pragma unroll
            for (int ntp = 0; ntp < 4; ntp++) {
                unsigned bh[4];
                LDSM4(bh, bb + ntp * 1280);
                float* a00 = &acc[(ntp * 2) * 4];
                float* a01 = &acc[(ntp * 2 + 1) * 4];
                float* a10 = &acc[(8 + ntp * 2) * 4];
                float* a11 = &acc[(8 + ntp * 2 + 1) * 4];
                MMA(a00, ah0, bh[0], bh[1]);
                MMA(a01, ah0, bh[2], bh[3]);
                MMA(a10, ah1, bh[0], bh[1]);
                MMA(a11, ah1, bh[2], bh[3]);
                MMA(a00, al0, bh[0], bh[1]);
                MMA(a01, al0, bh[2], bh[3]);
                MMA(a10, al1, bh[0], bh[1]);
                MMA(a11, al1, bh[2], bh[3]);
            }
        }
        __syncthreads();
    }

    // epilogue: acc -> g_conv[b][o][px] with bias
    int pxb = p0 + wm * 32 + (lane >> 2);
#pragma unroll
    for (int mt = 0; mt < 2; mt++) {
#pragma unroll
        for (int nt = 0; nt < 8; nt++) {
            float* ap = &acc[(mt * 8 + nt) * 4];
            int o = wn * 64 + nt * 8 + (lane & 3) * 2;
            float bv0 = __ldg(bias + o), bv1 = __ldg(bias + o + 1);
            int pxm = pxb + mt * 16;
            size_t r0 = (((size_t)(b * 256 + o)) << 12) + pxm;
            size_t r1 = r0 + 4096;
            g_conv[r0] = ap[0] + bv0;
            g_conv[r1] = ap[1] + bv1;
            g_conv[r0 + 8] = ap[2] + bv0;
            g_conv[r1 + 8] = ap[3] + bv1;
        }
    }
}

// ---------------------------------------------------------------------------
// GroupNorm statistics
// ---------------------------------------------------------------------------
__global__ void k_stats() {
    int bg = blockIdx.x;
    const float4* ptr = (const float4*)(g_conv + ((size_t)bg << 16));
    float s = 0.f, ss = 0.f;
    for (int i = threadIdx.x; i < 16384; i += 256) {
        float4 v = ptr[i];
        s += v.x + v.y + v.z + v.w;
        ss += v.x * v.x + v.y * v.y + v.z * v.z + v.w * v.w;
    }
    __shared__ float sh[512];
    sh[threadIdx.x] = s;
    sh[256 + threadIdx.x] = ss;
    __syncthreads();
    for (int st = 128; st > 0; st >>= 1) {
        if (threadIdx.x < st) {
            sh[threadIdx.x] += sh[threadIdx.x + st];
            sh[256 + threadIdx.x] += sh[256 + threadIdx.x + st];
        }
        __syncthreads();
    }
    if (threadIdx.x == 0) {
        float mu = sh[0] * (1.f / 65536.f);
        float var = sh[256] * (1.f / 65536.f) - mu * mu;
        g_mu[bg] = mu;
        g_rs[bg] = rsqrtf(var + 1e-5f);
    }
}

// ---------------------------------------------------------------------------
// Normalize + affine -> d_out
// ---------------------------------------------------------------------------
__global__ void k_norm(const float* __restrict__ gamma,
                       const float* __restrict__ beta,
                       float* __restrict__ out) {
    int i = blockIdx.x * 256 + threadIdx.x;
    float4 v = ((const float4*)g_conv)[i];
    int bc = i >> 10;
    int c = bc & 255, b = bc >> 8;
    int bg = b * 16 + (c >> 4);
    float sc = g_rs[bg] * gamma[c];
    float sh = beta[c] - g_mu[bg] * sc;
    v.x = v.x * sc + sh;
    v.y = v.y * sc + sh;
    v.z = v.z * sc + sh;
    v.w = v.w * sc + sh;
    ((float4*)out)[i] = v;
}

// ---------------------------------------------------------------------------
extern "C" void kernel_launch(void* const* d_in, const int* in_sizes, int n_in,
                              void* d_out, int out_size) {
    const float* x = nullptr;
    const float* w_off = nullptr;
    const float* b_off = nullptr;
    const float* weight = nullptr;
    const float* v256[3] = {nullptr, nullptr, nullptr};
    int n256 = 0;
    for (int i = 0; i < n_in; i++) {
        int s = in_sizes[i];
        const float* ptr = (const float*)d_in[i];
        if (s == 4194304) x = ptr;
        else if (s == 62208) w_off = ptr;
        else if (s == 27) b_off = ptr;
        else if (s == 589824) weight = ptr;
        else if (s == 256 && n256 < 3) v256[n256++] = ptr;
    }
    const float* bias  = v256[0];
    const float* gamma = v256[1];
    const float* beta  = v256[2];
    float* out = (float*)d_out;

    cudaFuncSetAttribute(k_mainTC, cudaFuncAttributeMaxDynamicSharedMemorySize,
                         SMEM_TOTAL);

    k_xT<<<4096, 256>>>(x);
    k_prepW<<<256, 256>>>(weight);
    k_offW<<<72, 256>>>(w_off);
    k_offGemm<<<128, 256>>>(b_off);
    k_mainTC<<<128, 512, SMEM_TOTAL>>>(bias);
    k_stats<<<64, 256>>>();
    k_norm<<<4096, 256>>>(gamma, beta, out);
}

// round 9
// speedup vs baseline: 3.2980x; 1.2065x over previous
#include <cuda_runtime.h>
#include <cuda_fp16.h>
#include <cstdint>

// ---------------------------------------------------------------------------
// DCNv2 + GroupNorm16.  B=4, Cin=Cout=256, H=W=64, K=3, s=1, p=1, g=16.
// One fused tensor-core kernel: phase1 = offset conv (HMMA, im2col A) with
// bilinear meta to smem; phase2 = deformable-sampled HMMA GEMM, A split
// hi/lo fp16 (2 terms), B single fp16. GN partial stats fused in epilogue.
// Harness compiles via compute_103 (no 'a') -> baseline PTX only.
// ---------------------------------------------------------------------------

// ---- device-global scratch -------------------------------------------------
__device__ float  g_xT[4 * 4096 * 256];       // x transposed to NHWC
__device__ __half g_wF16[72 * 256 * 32];      // main weight fp16 [ci][o][k]
__device__ __half g_wOf[72 * 32 * 32];        // offset weight fp16 [ci][o32][k]
__device__ float  g_conv[4 * 256 * 4096];     // conv out (pre-GN)
__device__ float  g_psum[64 * 32];            // per-(bg,tile) partial sums
__device__ float  g_pssum[64 * 32];
__device__ float  g_mu[64];
__device__ float  g_rs[64];

// ---- PTX helpers ----------------------------------------------------------
__device__ __forceinline__ unsigned smem_u32(const void* p) {
    unsigned a;
    asm("{ .reg .u64 t; cvta.to.shared.u64 t, %1; cvt.u32.u64 %0, t; }"
        : "=r"(a) : "l"(p));
    return a;
}
#define CP16(s, g) asm volatile("cp.async.cg.shared.global [%0], [%1], 16;" :: "r"(s), "l"(g) : "memory")
#define CP_COMMIT() asm volatile("cp.async.commit_group;" ::: "memory")
#define CP_WAIT0()  asm volatile("cp.async.wait_group 0;" ::: "memory")

#define LDSM4(r, addr)                                                        \
    asm volatile("ldmatrix.sync.aligned.m8n8.x4.shared.b16 {%0,%1,%2,%3}, [%4];" \
                 : "=r"((r)[0]), "=r"((r)[1]), "=r"((r)[2]), "=r"((r)[3])     \
                 : "r"(addr))

#define MMA(ap, a, b0, b1)                                                    \
    asm volatile("mma.sync.aligned.m16n8k16.row.col.f32.f16.f16.f32 "         \
                 "{%0,%1,%2,%3}, {%4,%5,%6,%7}, {%8,%9}, {%0,%1,%2,%3};"      \
                 : "+f"((ap)[0]), "+f"((ap)[1]), "+f"((ap)[2]), "+f"((ap)[3]) \
                 : "r"((a)[0]), "r"((a)[1]), "r"((a)[2]), "r"((a)[3]),        \
                   "r"(b0), "r"(b1))

__device__ __forceinline__ unsigned pack_h2(float s0, float s1) {
    __half2 h = __floats2half2_rn(s0, s1);
    return *reinterpret_cast<unsigned*>(&h);
}
__device__ __forceinline__ void split_pair(float s0, float s1,
                                           unsigned& hp, unsigned& lp) {
    __half h0 = __float2half(s0), h1 = __float2half(s1);
    __half2 hh = __halves2half2(h0, h1);
    hp = *reinterpret_cast<unsigned*>(&hh);
    lp = pack_h2(s0 - __half2float(h0), s1 - __half2float(h1));
}

// ---------------------------------------------------------------------------
// x NCHW -> NHWC transpose
// ---------------------------------------------------------------------------
__global__ void k_xT(const float* __restrict__ x) {
    __shared__ float t[32][33];
    int bx = blockIdx.x;
    int pxb = bx & 127, cb = (bx >> 7) & 7, b = bx >> 10;
    int tx = threadIdx.x & 31, ty = threadIdx.x >> 5;
#pragma unroll
    for (int i = 0; i < 4; i++) {
        int c = cb * 32 + ty + i * 8;
        t[ty + i * 8][tx] = x[(((size_t)(b * 256 + c)) << 12) + pxb * 32 + tx];
    }
    __syncthreads();
#pragma unroll
    for (int i = 0; i < 4; i++) {
        int px = pxb * 32 + ty + i * 8;
        g_xT[(((size_t)b << 12) + px) * 256 + cb * 32 + tx] = t[tx][ty + i * 8];
    }
}

// ---------------------------------------------------------------------------
// main weight [O][C][3][3] -> fp16 [ci][o][k32];  ci = tap*8+cb, c = cb*32+k
// ---------------------------------------------------------------------------
__global__ void k_prepW(const float* __restrict__ w) {
    int o = blockIdx.x;
    for (int idx = threadIdx.x; idx < 2304; idx += 256) {
        int ci = idx >> 5, k = idx & 31;
        int tap = ci >> 3, c = ((ci & 7) << 5) + k;
        g_wF16[(size_t)ci * 8192 + o * 32 + k] =
            __float2half(w[o * 2304 + c * 9 + tap]);
    }
}

// ---------------------------------------------------------------------------
// offset weight [27][C][3][3] -> fp16 [ci][o(32, >=27 zero)][k32]
// ---------------------------------------------------------------------------
__global__ void k_offW(const float* __restrict__ wof) {
    int ci = blockIdx.x;
    int tap = ci >> 3, cb = ci & 7;
    for (int i = threadIdx.x; i < 1024; i += 256) {
        int o = i >> 5, k = i & 31;
        int c = (cb << 5) + k;
        float v = (o < 27) ? wof[o * 2304 + c * 9 + tap] : 0.f;
        g_wOf[ci * 1024 + i] = __float2half(v);
    }
}

// ---------------------------------------------------------------------------
// Fused kernel. Grid 128 = (b, 32 px-tiles of 128). 512 threads.
// SMEM layout (dynamic, 118784 B):
//   SA[buf][term]: 128 rows x 80B = 10240 each  ->  [0, 40960)
//   SB[buf]:       256 rows x 80B = 20480 each  ->  [40960, 81920)
//     (phase1 uses first 2560 of each buf; om scratch 128x32 f32 at 40960)
//   META_I: idx[9][128][4] int   -> [81920, 100352)
//   META_W: wgt[9][128][4] float -> [100352, 118784)
// ---------------------------------------------------------------------------
#define SA(buf, term) ((buf) * 20480 + (term) * 10240)
#define SB(buf)       (40960 + (buf) * 20480)
#define META_I        81920
#define META_W        100352
#define SMEM_TOTAL    118784

__global__ __launch_bounds__(512, 1) void k_mainTC(const float* __restrict__ bof,
                                                   const float* __restrict__ bias) {
    extern __shared__ char sm[];
    unsigned smb = smem_u32(sm);
    int tid = threadIdx.x, lane = tid & 31, wid = tid >> 5;
    int b = blockIdx.x >> 5;
    int tile = blockIdx.x & 31;
    int p0 = tile << 7;

    const float* xb = g_xT + ((size_t)b << 20);
    int px = tid >> 2, oct = tid & 3;     // A staging role (both phases)
    unsigned aoff = (unsigned)((lane & 15) * 80 + (lane >> 4) * 16);
    unsigned boff = (unsigned)((lane & 7) * 80 + ((lane >> 3) & 1) * 16 +
                               (lane >> 4) * 640);
    unsigned ao = (unsigned)(px * 80 + oct * 16);

    // =======================================================================
    // Phase 1: offset conv HMMA.  16 warps = (wm1 0..7) x (wn1 0..1), 16x16.
    // =======================================================================
    {
        int wm1 = wid & 7, wn1 = wid >> 3;
        float acc1[2][4];
#pragma unroll
        for (int i = 0; i < 2; i++)
#pragma unroll
            for (int j = 0; j < 4; j++) acc1[i][j] = 0.f;

        int gp = p0 + px, h = gp >> 6, w = gp & 63;
        float4 v0, v1;
        auto loadA1 = [&](int ci) {
            int tap = ci >> 3, cb = ci & 7;
            int py = h + tap / 3 - 1, pxx = w + tap % 3 - 1;
            if (py >= 0 && py < 64 && pxx >= 0 && pxx < 64) {
                const float* s = xb + (((size_t)(py * 64 + pxx)) << 8) +
                                 (cb << 5) + (oct << 3);
                v0 = *(const float4*)s;
                v1 = *(const float4*)(s + 4);
            } else {
                v0 = v1 = make_float4(0.f, 0.f, 0.f, 0.f);
            }
        };
        auto storeA1 = [&](int buf) {
            unsigned hp[4], lp[4];
            split_pair(v0.x, v0.y, hp[0], lp[0]);
            split_pair(v0.z, v0.w, hp[1], lp[1]);
            split_pair(v1.x, v1.y, hp[2], lp[2]);
            split_pair(v1.z, v1.w, hp[3], lp[3]);
            *(uint4*)(sm + SA(buf, 0) + ao) = make_uint4(hp[0], hp[1], hp[2], hp[3]);
            *(uint4*)(sm + SA(buf, 1) + ao) = make_uint4(lp[0], lp[1], lp[2], lp[3]);
        };
        auto loadB1 = [&](int ci, int buf) {
            if (tid < 128) {
                int row = tid >> 2, q = tid & 3;
                CP16(smb + SB(buf) + row * 80 + q * 16,
                     g_wOf + ci * 1024 + row * 32 + q * 8);
            }
            CP_COMMIT();
        };

        loadA1(0);
        loadB1(0, 0);
#pragma unroll 1
        for (int ci = 0; ci < 72; ci++) {
            int buf = ci & 1;
            storeA1(buf);
            CP_WAIT0();
            __syncthreads();
            if (ci < 71) { loadA1(ci + 1); loadB1(ci + 1, buf ^ 1); }
            unsigned aB = smb + (unsigned)(buf * 20480 + wm1 * 1280) + aoff;
            unsigned bB = smb + (unsigned)SB(buf) + (unsigned)(wn1 * 1280) + boff;
#pragma unroll
            for (int ks = 0; ks < 2; ks++) {
                unsigned ah[4], al[4], bh[4];
                LDSM4(ah, aB + ks * 32);
                LDSM4(al, aB + 10240 + ks * 32);
                LDSM4(bh, bB + ks * 32);
                MMA(acc1[0], ah, bh[0], bh[1]);
                MMA(acc1[1], ah, bh[2], bh[3]);
                MMA(acc1[0], al, bh[0], bh[1]);
                MMA(acc1[1], al, bh[2], bh[3]);
            }
            __syncthreads();
        }
        // om scratch -> smem at SB(0) (128 x 32 f32)
        float* som = (float*)(sm + 40960);
        {
            int row = wm1 * 16 + (lane >> 2);
            int col = wn1 * 16 + (lane & 3) * 2;
#pragma unroll
            for (int nt = 0; nt < 2; nt++) {
                int c = col + nt * 8;
                som[row * 32 + c] = acc1[nt][0];
                som[row * 32 + c + 1] = acc1[nt][1];
                som[(row + 8) * 32 + c] = acc1[nt][2];
                som[(row + 8) * 32 + c + 1] = acc1[nt][3];
            }
        }
        __syncthreads();
        // bilinear meta -> smem META
        int* sIdx = (int*)(sm + META_I);
        float* sWgt = (float*)(sm + META_W);
        for (int idx = tid; idx < 1152; idx += 512) {
            int pr = idx / 9, k = idx - pr * 9;
            float ay = som[pr * 32 + k] + __ldg(bof + k);
            float ax = som[pr * 32 + k + 9] + __ldg(bof + k + 9);
            float am = som[pr * 32 + k + 18] + __ldg(bof + k + 18);
            float m = 1.f / (1.f + __expf(-am));
            int gp2 = p0 + pr, hh = gp2 >> 6, ww = gp2 & 63;
            float py = (float)(hh + k / 3 - 1) + ay;
            float pxx = (float)(ww + (k - (k / 3) * 3) - 1) + ax;
            float y0f = floorf(py), x0f = floorf(pxx);
            float wy1 = py - y0f, wx1 = pxx - x0f;
            int y0 = (int)y0f, x0 = (int)x0f;
            int mo = (k * 128 + pr) * 4;
#pragma unroll
            for (int j = 0; j < 4; j++) {
                int dy = j >> 1, dx = j & 1;
                int yy = y0 + dy, xx = x0 + dx;
                float wv = (dy ? wy1 : 1.f - wy1) * (dx ? wx1 : 1.f - wx1);
                bool valid = (yy >= 0) && (yy < 64) && (xx >= 0) && (xx < 64);
                int yc = min(max(yy, 0), 63), xc = min(max(xx, 0), 63);
                sIdx[mo + j] = yc * 64 + xc;
                sWgt[mo + j] = valid ? wv * m : 0.f;
            }
        }
        __syncthreads();
    }

    // =======================================================================
    // Phase 2: main deformable GEMM.  16 warps = (wm 0..3) x (wn 0..3), 32x64.
    // =======================================================================
    int wm = wid & 3, wn = wid >> 2;
    float acc[64];
#pragma unroll
    for (int i = 0; i < 64; i++) acc[i] = 0.f;

    int4 mi;
    float4 mw;
    float sampA[8];
    const int* sIdx = (const int*)(sm + META_I);
    const float* sWgt = (const float*)(sm + META_W);

    auto meta = [&](int tap) {
        mi = *(const int4*)(sIdx + (tap * 128 + px) * 4);
        mw = *(const float4*)(sWgt + (tap * 128 + px) * 4);
    };
    auto gather = [&](int cn) {
        const float* base = xb + ((cn & 7) << 5) + oct * 8;
        const float* pp = base + ((size_t)mi.x << 8);
        float4 u0 = *(const float4*)pp, u1 = *(const float4*)(pp + 4);
        sampA[0] = mw.x * u0.x; sampA[1] = mw.x * u0.y;
        sampA[2] = mw.x * u0.z; sampA[3] = mw.x * u0.w;
        sampA[4] = mw.x * u1.x; sampA[5] = mw.x * u1.y;
        sampA[6] = mw.x * u1.z; sampA[7] = mw.x * u1.w;
        pp = base + ((size_t)mi.y << 8);
        u0 = *(const float4*)pp; u1 = *(const float4*)(pp + 4);
        sampA[0] = fmaf(mw.y, u0.x, sampA[0]); sampA[1] = fmaf(mw.y, u0.y, sampA[1]);
        sampA[2] = fmaf(mw.y, u0.z, sampA[2]); sampA[3] = fmaf(mw.y, u0.w, sampA[3]);
        sampA[4] = fmaf(mw.y, u1.x, sampA[4]); sampA[5] = fmaf(mw.y, u1.y, sampA[5]);
        sampA[6] = fmaf(mw.y, u1.z, sampA[6]); sampA[7] = fmaf(mw.y, u1.w, sampA[7]);
        pp = base + ((size_t)mi.z << 8);
        u0 = *(const float4*)pp; u1 = *(const float4*)(pp + 4);
        sampA[0] = fmaf(mw.z, u0.x, sampA[0]); sampA[1] = fmaf(mw.z, u0.y, sampA[1]);
        sampA[2] = fmaf(mw.z, u0.z, sampA[2]); sampA[3] = fmaf(mw.z, u0.w, sampA[3]);
        sampA[4] = fmaf(mw.z, u1.x, sampA[4]); sampA[5] = fmaf(mw.z, u1.y, sampA[5]);
        sampA[6] = fmaf(mw.z, u1.z, sampA[6]); sampA[7] = fmaf(mw.z, u1.w, sampA[7]);
        pp = base + ((size_t)mi.w << 8);
        u0 = *(const float4*)pp; u1 = *(const float4*)(pp + 4);
        sampA[0] = fmaf(mw.w, u0.x, sampA[0]); sampA[1] = fmaf(mw.w, u0.y, sampA[1]);
        sampA[2] = fmaf(mw.w, u0.z, sampA[2]); sampA[3] = fmaf(mw.w, u0.w, sampA[3]);
        sampA[4] = fmaf(mw.w, u1.x, sampA[4]); sampA[5] = fmaf(mw.w, u1.y, sampA[5]);
        sampA[6] = fmaf(mw.w, u1.z, sampA[6]); sampA[7] = fmaf(mw.w, u1.w, sampA[7]);
    };
    auto loadB = [&](int ci, int buf) {
        if (tid < 256) {
            const __half* g = g_wF16 + (size_t)ci * 8192 + tid * 32;
            unsigned s = smb + SB(buf) + tid * 80;
            CP16(s, g); CP16(s + 16, g + 8);
            CP16(s + 32, g + 16); CP16(s + 48, g + 24);
        }
        CP_COMMIT();
    };

    meta(0);
    gather(0);
    loadB(0, 0);

#pragma unroll 1
    for (int ci = 0; ci < 72; ci++) {
        int buf = ci & 1;
        {
            unsigned hp[4], lp[4];
            split_pair(sampA[0], sampA[1], hp[0], lp[0]);
            split_pair(sampA[2], sampA[3], hp[1], lp[1]);
            split_pair(sampA[4], sampA[5], hp[2], lp[2]);
            split_pair(sampA[6], sampA[7], hp[3], lp[3]);
            *(uint4*)(sm + SA(buf, 0) + ao) = make_uint4(hp[0], hp[1], hp[2], hp[3]);
            *(uint4*)(sm + SA(buf, 1) + ao) = make_uint4(lp[0], lp[1], lp[2], lp[3]);
        }
        CP_WAIT0();
        __syncthreads();

        if (ci < 71) {
            int cn = ci + 1;
            if ((cn & 7) == 0) meta(cn >> 3);
            gather(cn);
            loadB(cn, buf ^ 1);
        }

#pragma unroll
        for (int ks = 0; ks < 2; ks++) {
            unsigned ab = smb + (unsigned)(buf * 20480 + wm * 2560 + ks * 32) + aoff;
            unsigned ah0[4], ah1[4], al0[4], al1[4];
            LDSM4(ah0, ab);
            LDSM4(ah1, ab + 1280);
            LDSM4(al0, ab + 10240);
            LDSM4(al1, ab + 11520);
            unsigned bb = smb + (unsigned)(SB(buf) + wn * 5120 + ks * 32) + boff;
#pragma unroll
            for (int ntp = 0; ntp < 4; ntp++) {
                unsigned bh[4];
                LDSM4(bh, bb + ntp * 1280);
                float* a00 = &acc[(ntp * 2) * 4];
                float* a01 = &acc[(ntp * 2 + 1) * 4];
                float* a10 = &acc[(8 + ntp * 2) * 4];
                float* a11 = &acc[(8 + ntp * 2 + 1) * 4];
                MMA(a00, ah0, bh[0], bh[1]);
                MMA(a01, ah0, bh[2], bh[3]);
                MMA(a10, ah1, bh[0], bh[1]);
                MMA(a11, ah1, bh[2], bh[3]);
                MMA(a00, al0, bh[0], bh[1]);
                MMA(a01, al0, bh[2], bh[3]);
                MMA(a10, al1, bh[0], bh[1]);
                MMA(a11, al1, bh[2], bh[3]);
            }
        }
        __syncthreads();
    }

    // ---- epilogue: bias add, store, fused GN partial stats ----
    float pg[4] = {0.f, 0.f, 0.f, 0.f};
    float pq[4] = {0.f, 0.f, 0.f, 0.f};
    int pxb = p0 + wm * 32 + (lane >> 2);
#pragma unroll
    for (int mt = 0; mt < 2; mt++) {
#pragma unroll
        for (int nt = 0; nt < 8; nt++) {
            float* ap = &acc[(mt * 8 + nt) * 4];
            int o = wn * 64 + nt * 8 + (lane & 3) * 2;
            float bv0 = __ldg(bias + o), bv1 = __ldg(bias + o + 1);
            int pxm = pxb + mt * 16;
            size_t r0 = (((size_t)(b * 256 + o)) << 12) + pxm;
            size_t r1 = r0 + 4096;
            float v0 = ap[0] + bv0, v1 = ap[1] + bv1;
            float v2 = ap[2] + bv0, v3 = ap[3] + bv1;
            g_conv[r0] = v0;
            g_conv[r1] = v1;
            g_conv[r0 + 8] = v2;
            g_conv[r1 + 8] = v3;
            int j = nt >> 1;
            pg[j] += v0 + v1 + v2 + v3;
            pq[j] += v0 * v0 + v1 * v1 + v2 * v2 + v3 * v3;
        }
    }
    // warp reduce 8 values
#pragma unroll
    for (int j = 0; j < 4; j++) {
#pragma unroll
        for (int s = 16; s > 0; s >>= 1) {
            pg[j] += __shfl_down_sync(0xFFFFFFFFu, pg[j], s);
            pq[j] += __shfl_down_sync(0xFFFFFFFFu, pq[j], s);
        }
    }
    float* red = (float*)sm;   // 16 warps x 8 floats
    if (lane == 0) {
#pragma unroll
        for (int j = 0; j < 4; j++) {
            red[wid * 8 + j] = pg[j];
            red[wid * 8 + 4 + j] = pq[j];
        }
    }
    __syncthreads();
    if (tid < 32) {
        int group = tid >> 1, which = tid & 1;   // 16 groups x {sum,ssum}
        int wnb = group >> 2;
        float v = 0.f;
#pragma unroll
        for (int wmi = 0; wmi < 4; wmi++)
            v += red[(wnb * 4 + wmi) * 8 + (group & 3) + 4 * which];
        if (which == 0) g_psum[(b * 16 + group) * 32 + tile] = v;
        else            g_pssum[(b * 16 + group) * 32 + tile] = v;
    }
}

// ---------------------------------------------------------------------------
// GN stats finalize: 64 blocks x 32 threads
// ---------------------------------------------------------------------------
__global__ void k_statsF() {
    int bg = blockIdx.x, t = threadIdx.x;
    float s = g_psum[bg * 32 + t];
    float q = g_pssum[bg * 32 + t];
#pragma unroll
    for (int o = 16; o > 0; o >>= 1) {
        s += __shfl_down_sync(0xFFFFFFFFu, s, o);
        q += __shfl_down_sync(0xFFFFFFFFu, q, o);
    }
    if (t == 0) {
        float mu = s * (1.f / 65536.f);
        float var = q * (1.f / 65536.f) - mu * mu;
        g_mu[bg] = mu;
        g_rs[bg] = rsqrtf(var + 1e-5f);
    }
}

// ---------------------------------------------------------------------------
// Normalize + affine -> d_out.  2048 blocks x 256 thr x 2 float4.
// ---------------------------------------------------------------------------
__global__ void k_norm(const float* __restrict__ gamma,
                       const float* __restrict__ beta,
                       float* __restrict__ out) {
    int i = blockIdx.x * 512 + threadIdx.x;
#pragma unroll
    for (int t = 0; t < 2; t++, i += 256) {
        float4 v = ((const float4*)g_conv)[i];
        int bc = i >> 10;
        int c = bc & 255, b = bc >> 8;
        int bg = b * 16 + (c >> 4);
        float sc = g_rs[bg] * gamma[c];
        float sh = beta[c] - g_mu[bg] * sc;
        v.x = v.x * sc + sh;
        v.y = v.y * sc + sh;
        v.z = v.z * sc + sh;
        v.w = v.w * sc + sh;
        ((float4*)out)[i] = v;
    }
}

// ---------------------------------------------------------------------------
extern "C" void kernel_launch(void* const* d_in, const int* in_sizes, int n_in,
                              void* d_out, int out_size) {
    const float* x = nullptr;
    const float* w_off = nullptr;
    const float* b_off = nullptr;
    const float* weight = nullptr;
    const float* v256[3] = {nullptr, nullptr, nullptr};
    int n256 = 0;
    for (int i = 0; i < n_in; i++) {
        int s = in_sizes[i];
        const float* ptr = (const float*)d_in[i];
        if (s == 4194304) x = ptr;
        else if (s == 62208) w_off = ptr;
        else if (s == 27) b_off = ptr;
        else if (s == 589824) weight = ptr;
        else if (s == 256 && n256 < 3) v256[n256++] = ptr;
    }
    const float* bias  = v256[0];
    const float* gamma = v256[1];
    const float* beta  = v256[2];
    float* out = (float*)d_out;

    cudaFuncSetAttribute(k_mainTC, cudaFuncAttributeMaxDynamicSharedMemorySize,
                         SMEM_TOTAL);

    k_xT<<<4096, 256>>>(x);
    k_prepW<<<256, 256>>>(weight);
    k_offW<<<72, 256>>>(w_off);
    k_mainTC<<<128, 512, SMEM_TOTAL>>>(b_off, bias);
    k_statsF<<<64, 32>>>();
    k_norm<<<2048, 256>>>(gamma, beta, out);
}